// round 15
// baseline (speedup 1.0000x reference)
#include <cuda_runtime.h>
#include <cuda_fp16.h>
#include <math.h>
#include <stdint.h>

// Problem dims (fixed)
#define B_SZ 4
#define L_SZ 4096
#define DM   1024
#define DS   256
#define DH   4096
#define M_ROWS (B_SZ * L_SZ)   // 16384
#define CH     32
#define NCHUNK (L_SZ / CH)     // 128

// ---------------- scratch (device globals; no allocations) ------------------
__device__ __half g_xh  [(size_t)M_ROWS * DM];     // x in fp16
__device__ __half g_Bu  [(size_t)M_ROWS * 512];    // Bu GEMM output (fp16)
__device__ __half g_S   [(size_t)M_ROWS * 512];    // scan states sr|si (fp16)
__device__ __half g_y   [(size_t)M_ROWS * DM];
__device__ __half g_h   [(size_t)M_ROWS * DH];
__device__ __half g_Bcat[512 * DM];                // gamma*(Bre;Bim)
__device__ __half g_Ccat[DM * 512];                // [1024, 512] Cre|-Cim
__device__ __half g_Dh  [(size_t)DM * DM];         // D fp16
__device__ __half g_W1T [(size_t)DH * DM];
__device__ __half g_W2T [(size_t)DM * DH];
__device__ float2 g_lam[DS];
__device__ float  g_gamma[DS];
__device__ float2 g_final[B_SZ * NCHUNK * DS];
__device__ float2 g_carry[B_SZ * NCHUNK * DS];

// ---------------- helpers ----------------------------------------------------
__device__ __forceinline__ uint32_t smem_u32(const void* p) {
    uint32_t a;
    asm("{ .reg .u64 t; cvta.to.shared.u64 t, %1; cvt.u32.u64 %0, t; }" : "=r"(a) : "l"(p));
    return a;
}
__device__ __forceinline__ void cp_async16(uint32_t saddr, const void* gaddr) {
    asm volatile("cp.async.cg.shared.global [%0], [%1], 16;" :: "r"(saddr), "l"(gaddr));
}
__device__ __forceinline__ void cp_commit() {
    asm volatile("cp.async.commit_group;" ::: "memory");
}
__device__ __forceinline__ void cp_wait3() {
    asm volatile("cp.async.wait_group 3;" ::: "memory");
}
__device__ __forceinline__ void mma_f16(float* d, const uint32_t* a, const uint32_t* b) {
    asm volatile(
        "mma.sync.aligned.m16n8k16.row.col.f32.f16.f16.f32 "
        "{%0,%1,%2,%3}, {%4,%5,%6,%7}, {%8,%9}, {%0,%1,%2,%3};"
        : "+f"(d[0]), "+f"(d[1]), "+f"(d[2]), "+f"(d[3])
        : "r"(a[0]), "r"(a[1]), "r"(a[2]), "r"(a[3]),
          "r"(b[0]), "r"(b[1]));
}
__device__ __forceinline__ void ldsm_x4(uint32_t& r0, uint32_t& r1,
                                        uint32_t& r2, uint32_t& r3, uint32_t addr) {
    asm volatile("ldmatrix.sync.aligned.m8n8.x4.shared.b16 {%0,%1,%2,%3}, [%4];"
                 : "=r"(r0), "=r"(r1), "=r"(r2), "=r"(r3) : "r"(addr));
}

enum { EPI_F32 = 0, EPI_HALF = 1, EPI_GELUH = 2, EPI_RESID = 3, EPI_ADDH = 4 };

// ---------------- prep kernels ----------------------------------------------
__global__ void precompute_k(const float* __restrict__ nu_log,
                             const float* __restrict__ theta_log) {
    int n = threadIdx.x;
    float nu  = expf(nu_log[n]);
    float th  = expf(theta_log[n]);
    float mag = expf(-nu);
    g_lam[n]   = make_float2(mag * cosf(th), mag * sinf(th));
    g_gamma[n] = sqrtf(fmaxf(0.f, 1.f - mag * mag));
}

__global__ void prep_bcat_k(const float* __restrict__ Bre, const float* __restrict__ Bim) {
    int idx = blockIdx.x * blockDim.x + threadIdx.x;   // over 512*1024
    int n = idx >> 10, k = idx & 1023;
    float v = (n < 256) ? g_gamma[n] * Bre[n * DM + k]
                        : g_gamma[n - 256] * Bim[(n - 256) * DM + k];
    g_Bcat[idx] = __float2half_rn(v);
}

__global__ void prep_ccat_k(const float* __restrict__ Cre, const float* __restrict__ Cim) {
    int idx = blockIdx.x * blockDim.x + threadIdx.x;   // over 1024*512
    int n = idx >> 9, k = idx & 511;
    float v = (k < 256) ? Cre[n * DS + k] : -Cim[n * DS + (k - 256)];
    g_Ccat[idx] = __float2half_rn(v);
}

__global__ void prep_dh_k(const float* __restrict__ Dm) {
    size_t idx = (size_t)blockIdx.x * blockDim.x + threadIdx.x;   // over 1024*1024
    g_Dh[idx] = __float2half_rn(Dm[idx]);
}

__global__ void transpose_k(const float* __restrict__ in, __half* __restrict__ out,
                            int R, int Cc) {   // out[c*R+r] = h(in[r*Cc+c])
    __shared__ float t[32][33];
    int c0 = blockIdx.x * 32, r0 = blockIdx.y * 32;
    int x = threadIdx.x, y0 = threadIdx.y;
    for (int yy = y0; yy < 32; yy += 8)
        t[yy][x] = in[(size_t)(r0 + yy) * Cc + c0 + x];
    __syncthreads();
    for (int yy = y0; yy < 32; yy += 8)
        out[(size_t)(c0 + yy) * R + r0 + x] = __float2half_rn(t[x][yy]);
}

__global__ void xcopy_k(const float* __restrict__ x) {  // x -> g_xh (fp16)
    size_t i = (size_t)blockIdx.x * blockDim.x + threadIdx.x;   // over M*DM/8
    size_t el = i * 8;
    const float4 v0 = ((const float4*)(x + el))[0];
    const float4 v1 = ((const float4*)(x + el))[1];
    __half2 h0 = __floats2half2_rn(v0.x, v0.y);
    __half2 h1 = __floats2half2_rn(v0.z, v0.w);
    __half2 h2 = __floats2half2_rn(v1.x, v1.y);
    __half2 h3 = __floats2half2_rn(v1.z, v1.w);
    uint4 pk;
    pk.x = *(uint32_t*)&h0; pk.y = *(uint32_t*)&h1;
    pk.z = *(uint32_t*)&h2; pk.w = *(uint32_t*)&h3;
    *(uint4*)(g_xh + el) = pk;
}

// ---------------- fp16 mma.sync GEMM: 128x128x32 + ldmatrix, 5-stage ---------
#define BM 128
#define BN 128
#define BK 32
#define STG 5
#define PADKh 40
#define TILE_H (128 * PADKh)               // 5120 halves
#define STAGE_H (2 * TILE_H)               // 10240 halves
#define SMEM_BYTES (STG * STAGE_H * 2)     // 102400 -> 2 CTAs/SM (200KB)

template<int EPI>
__global__ __launch_bounds__(256, 2)
void mma_gemm(const __half* __restrict__ A, const __half* __restrict__ Bw,
              void* __restrict__ Cv, int N, int K, int lda,
              const float* __restrict__ X, const float* __restrict__ res_logit)
{
    extern __shared__ __half smh[];
    const int tid  = threadIdx.x;
    const int wid  = tid >> 5, lane = tid & 31;
    const int m0 = blockIdx.y * BM, n0 = blockIdx.x * BN;
    const int wm = (wid & 3) * 32, wn = (wid >> 2) * 64;
    const int r = lane >> 2, cq = lane & 3;

    const int lr = tid >> 1;
    const int lch = (tid & 1) * 16;
    const __half* Ag = A + (size_t)(m0 + lr) * lda + lch;
    const __half* Bg = Bw + (size_t)(n0 + lr) * K + lch;
    const uint32_t sbase = smem_u32(smh);
    const uint32_t sAoff = (lr * PADKh + lch) * 2;
    const uint32_t sBoff = (TILE_H + lr * PADKh + lch) * 2;

    // ldmatrix per-lane offset (bytes): row = lane&15, k-half = (lane>>4)*8
    const uint32_t lmoff = (((lane & 15) * PADKh) + (lane >> 4) * 8) * 2;

    float acc[2][8][4];
#pragma unroll
    for (int mt = 0; mt < 2; mt++)
#pragma unroll
        for (int nt = 0; nt < 8; nt++)
#pragma unroll
            for (int i = 0; i < 4; i++) acc[mt][nt][i] = 0.f;

    const int KT = K / BK;

#pragma unroll
    for (int s = 0; s < STG - 1; s++) {
        const int k0 = s * BK;
        const uint32_t sb = sbase + s * STAGE_H * 2;
        cp_async16(sb + sAoff,      Ag + k0);
        cp_async16(sb + sAoff + 16, Ag + k0 + 8);
        cp_async16(sb + sBoff,      Bg + k0);
        cp_async16(sb + sBoff + 16, Bg + k0 + 8);
        cp_commit();
    }

    for (int kt = 0; kt < KT; kt++) {
        cp_wait3();           // stage kt resident (<= STG-2 groups outstanding)
        __syncthreads();      // stage kt-1 slot free

        const int kp = kt + STG - 1;
        if (kp < KT) {
            const int k0 = kp * BK;
            const uint32_t sb = sbase + (kp % STG) * STAGE_H * 2;
            cp_async16(sb + sAoff,      Ag + k0);
            cp_async16(sb + sAoff + 16, Ag + k0 + 8);
            cp_async16(sb + sBoff,      Bg + k0);
            cp_async16(sb + sBoff + 16, Bg + k0 + 8);
        }
        cp_commit();

        const uint32_t sAb = sbase + (kt % STG) * STAGE_H * 2;
        const uint32_t sBb = sAb + TILE_H * 2;
#pragma unroll
        for (int ks = 0; ks < 2; ks++) {
            uint32_t af[2][4], bf[8][2];
#pragma unroll
            for (int mt = 0; mt < 2; mt++) {
                const uint32_t addr = sAb + ((wm + mt * 16) * PADKh + ks * 16) * 2 + lmoff;
                ldsm_x4(af[mt][0], af[mt][1], af[mt][2], af[mt][3], addr);
            }
#pragma unroll
            for (int ntp = 0; ntp < 4; ntp++) {
                const uint32_t addr = sBb + ((wn + ntp * 16) * PADKh + ks * 16) * 2 + lmoff;
                ldsm_x4(bf[2 * ntp][0], bf[2 * ntp + 1][0],
                        bf[2 * ntp][1], bf[2 * ntp + 1][1], addr);
            }
#pragma unroll
            for (int mt = 0; mt < 2; mt++)
#pragma unroll
                for (int nt = 0; nt < 8; nt++)
                    mma_f16(acc[mt][nt], af[mt], bf[nt]);
        }
    }

    float sig = 0.f;
    if (EPI == EPI_RESID) sig = 1.f / (1.f + expf(-res_logit[0]));

#pragma unroll
    for (int mt = 0; mt < 2; mt++)
#pragma unroll
        for (int nt = 0; nt < 8; nt++) {
            const int row = m0 + wm + mt * 16 + r;
            const int col = n0 + wn + nt * 8 + cq * 2;
#pragma unroll
            for (int h = 0; h < 2; h++) {
                const size_t off = (size_t)(row + h * 8) * N + col;
                float v0 = acc[mt][nt][h * 2 + 0];
                float v1 = acc[mt][nt][h * 2 + 1];
                if (EPI == EPI_F32) {
                    *(float2*)((float*)Cv + off) = make_float2(v0, v1);
                } else if (EPI == EPI_HALF) {
                    *(__half2*)((__half*)Cv + off) = __floats2half2_rn(v0, v1);
                } else if (EPI == EPI_ADDH) {
                    __half2 old = *(__half2*)((__half*)Cv + off);
                    float2 of = __half22float2(old);
                    *(__half2*)((__half*)Cv + off) = __floats2half2_rn(of.x + v0, of.y + v1);
                } else if (EPI == EPI_GELUH) {
                    float g0 = 0.5f * v0 * (1.f + tanhf(0.7978845608028654f * (v0 + 0.044715f * v0 * v0 * v0)));
                    float g1 = 0.5f * v1 * (1.f + tanhf(0.7978845608028654f * (v1 + 0.044715f * v1 * v1 * v1)));
                    *(__half2*)((__half*)Cv + off) = __floats2half2_rn(g0, g1);
                } else {
                    float2 xv = *(const float2*)(X + off);
                    *(float2*)((float*)Cv + off) =
                        make_float2(xv.x + sig * v0, xv.y + sig * v1);
                }
            }
        }
}

// ---------------- chunked complex scan (fp32 arithmetic, fp16 I/O) -----------
__device__ __forceinline__ float2 cmul(float2 a, float2 b) {
    return make_float2(a.x * b.x - a.y * b.y, a.x * b.y + a.y * b.x);
}

__global__ void scan1_k() {
    int b = blockIdx.y, chk = blockIdx.x, n = threadIdx.x;
    float2 lam = g_lam[n];
    float2 s = make_float2(0.f, 0.f);
    size_t base = ((size_t)(b * L_SZ + chk * CH)) * 512;
    for (int i = 0; i < CH; i++) {
        size_t ib = base + (size_t)i * 512;
        float ur = __half2float(g_Bu[ib + n]);
        float ui = __half2float(g_Bu[ib + 256 + n]);
        s = make_float2(lam.x * s.x - lam.y * s.y + ur,
                        lam.x * s.y + lam.y * s.x + ui);
    }
    g_final[(b * NCHUNK + chk) * DS + n] = s;
}

__global__ void scan2_k() {
    int b = blockIdx.x, n = threadIdx.x;
    float2 lam = g_lam[n];
    float2 lc = lam;
#pragma unroll
    for (int t = 0; t < 5; t++) lc = cmul(lc, lc);   // lam^32 (CH = 32 = 2^5)
    float2 c = make_float2(0.f, 0.f);
    for (int j = 0; j < NCHUNK; j++) {
        g_carry[(b * NCHUNK + j) * DS + n] = c;
        float2 f = g_final[(b * NCHUNK + j) * DS + n];
        c = make_float2(lc.x * c.x - lc.y * c.y + f.x,
                        lc.x * c.y + lc.y * c.x + f.y);
    }
}

__global__ void scan3_k(float* __restrict__ st_out, int st_mode) {
    int b = blockIdx.y, chk = blockIdx.x, n = threadIdx.x;
    float2 lam = g_lam[n];
    float2 s = g_carry[(b * NCHUNK + chk) * DS + n];
    size_t base = ((size_t)(b * L_SZ + chk * CH)) * 512;
    for (int i = 0; i < CH; i++) {
        size_t ib = base + (size_t)i * 512;
        float ur = __half2float(g_Bu[ib + n]);
        float ui = __half2float(g_Bu[ib + 256 + n]);
        s = make_float2(lam.x * s.x - lam.y * s.y + ur,
                        lam.x * s.y + lam.y * s.x + ui);
        g_S[ib + n]       = __float2half_rn(s.x);
        g_S[ib + 256 + n] = __float2half_rn(s.y);
    }
    if (chk == NCHUNK - 1 && st_mode > 0) {
        st_out[b * DS + n] = s.x;
        if (st_mode == 2) st_out[B_SZ * DS + b * DS + n] = s.y;
    }
}

// ---------------- launch ----------------------------------------------------
extern "C" void kernel_launch(void* const* d_in, const int* in_sizes, int n_in,
                              void* d_out, int out_size)
{
    const float* x    = (const float*)d_in[0];
    const float* nu   = (const float*)d_in[1];
    const float* th   = (const float*)d_in[2];
    const float* Bre  = (const float*)d_in[3];
    const float* Bim  = (const float*)d_in[4];
    const float* Cre  = (const float*)d_in[5];
    const float* Cim  = (const float*)d_in[6];
    const float* Dm   = (const float*)d_in[7];
    const float* W1   = (const float*)d_in[8];
    const float* W2   = (const float*)d_in[9];
    const float* rlog = (const float*)d_in[10];
    float* out = (float*)d_out;

    __half *xh, *bu, *S, *y, *h, *bcat, *ccat, *dh, *w1t, *w2t;
    cudaGetSymbolAddress((void**)&xh,   g_xh);
    cudaGetSymbolAddress((void**)&bu,   g_Bu);
    cudaGetSymbolAddress((void**)&S,    g_S);
    cudaGetSymbolAddress((void**)&y,    g_y);
    cudaGetSymbolAddress((void**)&h,    g_h);
    cudaGetSymbolAddress((void**)&bcat, g_Bcat);
    cudaGetSymbolAddress((void**)&ccat, g_Ccat);
    cudaGetSymbolAddress((void**)&dh,   g_Dh);
    cudaGetSymbolAddress((void**)&w1t,  g_W1T);
    cudaGetSymbolAddress((void**)&w2t,  g_W2T);

    cudaFuncSetAttribute(mma_gemm<EPI_HALF>,  cudaFuncAttributeMaxDynamicSharedMemorySize, SMEM_BYTES);
    cudaFuncSetAttribute(mma_gemm<EPI_ADDH>,  cudaFuncAttributeMaxDynamicSharedMemorySize, SMEM_BYTES);
    cudaFuncSetAttribute(mma_gemm<EPI_GELUH>, cudaFuncAttributeMaxDynamicSharedMemorySize, SMEM_BYTES);
    cudaFuncSetAttribute(mma_gemm<EPI_RESID>, cudaFuncAttributeMaxDynamicSharedMemorySize, SMEM_BYTES);

    static cudaStream_t s_side = 0;
    static cudaEvent_t ev_fork = 0, ev_x = 0, ev_join = 0;
    if (s_side == 0) {
        cudaStreamCreateWithFlags(&s_side, cudaStreamNonBlocking);
        cudaEventCreateWithFlags(&ev_fork, cudaEventDisableTiming);
        cudaEventCreateWithFlags(&ev_x,    cudaEventDisableTiming);
        cudaEventCreateWithFlags(&ev_join, cudaEventDisableTiming);
    }

    // fork side stream at entry (weight prep independent of main chain)
    cudaEventRecord(ev_fork, 0);
    cudaStreamWaitEvent(s_side, ev_fork, 0);
    prep_dh_k<<<(DM * DM) / 256, 256, 0, s_side>>>(Dm);
    prep_ccat_k<<<(DM * 512) / 256, 256, 0, s_side>>>(Cre, Cim);
    transpose_k<<<dim3(DH / 32, DM / 32), dim3(32, 8), 0, s_side>>>(W1, w1t, DM, DH);
    transpose_k<<<dim3(DM / 32, DH / 32), dim3(32, 8), 0, s_side>>>(W2, w2t, DH, DM);

    // main chain: lam/gamma -> Bcat, xh
    precompute_k<<<1, DS>>>(nu, th);
    prep_bcat_k<<<(512 * DM) / 256, 256>>>(Bre, Bim);
    xcopy_k<<<((size_t)M_ROWS * DM / 8) / 256, 256>>>(x);
    cudaEventRecord(ev_x, 0);

    // side: y1 = xh @ D^T (independent of scan; overlaps Bu GEMM + scan)
    cudaStreamWaitEvent(s_side, ev_x, 0);
    mma_gemm<EPI_HALF><<<dim3(DM / BN, M_ROWS / BM), 256, SMEM_BYTES, s_side>>>(
        xh, dh, y, DM, DM, DM, nullptr, nullptr);
    cudaEventRecord(ev_join, s_side);

    // main: Bu GEMM -> scan
    mma_gemm<EPI_HALF><<<dim3(512 / BN, M_ROWS / BM), 256, SMEM_BYTES>>>(
        xh, bcat, bu, 512, DM, DM, nullptr, nullptr);
    scan1_k<<<dim3(NCHUNK, B_SZ), DS>>>();
    scan2_k<<<B_SZ, DS>>>();
    long long tail = (long long)out_size - (long long)M_ROWS * DM;
    int st_mode = (tail >= 2 * B_SZ * DS) ? 2 : (tail >= B_SZ * DS ? 1 : 0);
    scan3_k<<<dim3(NCHUNK, B_SZ), DS>>>(out + (size_t)M_ROWS * DM, st_mode);

    // join: y2 needs y1 (and Ccat)
    cudaStreamWaitEvent(0, ev_join, 0);

    // y += S @ Ccat^T   (K=512, read-modify-write fp16)
    mma_gemm<EPI_ADDH><<<dim3(DM / BN, M_ROWS / BM), 256, SMEM_BYTES>>>(
        S, ccat, y, DM, 512, 512, nullptr, nullptr);

    // h = gelu(y @ W1T^T)
    mma_gemm<EPI_GELUH><<<dim3(DH / BN, M_ROWS / BM), 256, SMEM_BYTES>>>(
        y, w1t, h, DH, DM, DM, nullptr, nullptr);

    // out = x + sigmoid(res_logit) * (h @ W2T^T)
    mma_gemm<EPI_RESID><<<dim3(DM / BN, M_ROWS / BM), 256, SMEM_BYTES>>>(
        h, w2t, out, DM, DH, DH, x, rlog);
}

// round 16
// speedup vs baseline: 1.0242x; 1.0242x over previous
#include <cuda_runtime.h>
#include <cuda_fp16.h>
#include <math.h>
#include <stdint.h>

// Problem dims (fixed)
#define B_SZ 4
#define L_SZ 4096
#define DM   1024
#define DS   256
#define DH   4096
#define M_ROWS (B_SZ * L_SZ)   // 16384
#define CH     32
#define NCHUNK (L_SZ / CH)     // 128

// ---------------- scratch (device globals; no allocations) ------------------
__device__ __half g_xh  [(size_t)M_ROWS * DM];     // x in fp16
__device__ __half g_Bu  [(size_t)M_ROWS * 512];    // Bu GEMM output (fp16)
__device__ __half g_S   [(size_t)M_ROWS * 512];    // scan states sr|si (fp16)
__device__ __half g_y   [(size_t)M_ROWS * DM];
__device__ __half g_h   [(size_t)M_ROWS * DH];
__device__ __half g_Bcat[512 * DM];                // gamma*(Bre;Bim)
__device__ __half g_Ccat[DM * 512];                // [1024, 512] Cre|-Cim
__device__ __half g_Dh  [(size_t)DM * DM];         // D fp16
__device__ __half g_W1T [(size_t)DH * DM];
__device__ __half g_W2T [(size_t)DM * DH];
__device__ float2 g_lam[DS];
__device__ float  g_gamma[DS];
__device__ float2 g_final[B_SZ * NCHUNK * DS];
__device__ float2 g_carry[B_SZ * NCHUNK * DS];

// ---------------- helpers ----------------------------------------------------
__device__ __forceinline__ uint32_t smem_u32(const void* p) {
    uint32_t a;
    asm("{ .reg .u64 t; cvta.to.shared.u64 t, %1; cvt.u32.u64 %0, t; }" : "=r"(a) : "l"(p));
    return a;
}
__device__ __forceinline__ void cp_async16(uint32_t saddr, const void* gaddr) {
    asm volatile("cp.async.cg.shared.global [%0], [%1], 16;" :: "r"(saddr), "l"(gaddr));
}
__device__ __forceinline__ void cp_commit() {
    asm volatile("cp.async.commit_group;" ::: "memory");
}
__device__ __forceinline__ void cp_wait2() {
    asm volatile("cp.async.wait_group 2;" ::: "memory");
}
__device__ __forceinline__ void mma_f16(float* d, const uint32_t* a, const uint32_t* b) {
    asm volatile(
        "mma.sync.aligned.m16n8k16.row.col.f32.f16.f16.f32 "
        "{%0,%1,%2,%3}, {%4,%5,%6,%7}, {%8,%9}, {%0,%1,%2,%3};"
        : "+f"(d[0]), "+f"(d[1]), "+f"(d[2]), "+f"(d[3])
        : "r"(a[0]), "r"(a[1]), "r"(a[2]), "r"(a[3]),
          "r"(b[0]), "r"(b[1]));
}
__device__ __forceinline__ void ldsm_x4(uint32_t& r0, uint32_t& r1,
                                        uint32_t& r2, uint32_t& r3, uint32_t addr) {
    asm volatile("ldmatrix.sync.aligned.m8n8.x4.shared.b16 {%0,%1,%2,%3}, [%4];"
                 : "=r"(r0), "=r"(r1), "=r"(r2), "=r"(r3) : "r"(addr));
}
__device__ __forceinline__ float tanh_fast(float x) {
    float r;
    asm("tanh.approx.f32 %0, %1;" : "=f"(r) : "f"(x));
    return r;
}
__device__ __forceinline__ float gelu_fast(float v) {
    float u = 0.7978845608028654f * (v + 0.044715f * v * v * v);
    return 0.5f * v * (1.f + tanh_fast(u));
}

enum { EPI_F32 = 0, EPI_HALF = 1, EPI_GELUH = 2, EPI_RESID = 3, EPI_ADDH = 4 };

// ---------------- prep kernels ----------------------------------------------
__global__ void precompute_k(const float* __restrict__ nu_log,
                             const float* __restrict__ theta_log) {
    int n = threadIdx.x;
    float nu  = expf(nu_log[n]);
    float th  = expf(theta_log[n]);
    float mag = expf(-nu);
    g_lam[n]   = make_float2(mag * cosf(th), mag * sinf(th));
    g_gamma[n] = sqrtf(fmaxf(0.f, 1.f - mag * mag));
}

__global__ void prep_bcat_k(const float* __restrict__ Bre, const float* __restrict__ Bim) {
    int idx = blockIdx.x * blockDim.x + threadIdx.x;   // over 512*1024
    int n = idx >> 10, k = idx & 1023;
    float v = (n < 256) ? g_gamma[n] * Bre[n * DM + k]
                        : g_gamma[n - 256] * Bim[(n - 256) * DM + k];
    g_Bcat[idx] = __float2half_rn(v);
}

__global__ void prep_ccat_k(const float* __restrict__ Cre, const float* __restrict__ Cim) {
    int idx = blockIdx.x * blockDim.x + threadIdx.x;   // over 1024*512
    int n = idx >> 9, k = idx & 511;
    float v = (k < 256) ? Cre[n * DS + k] : -Cim[n * DS + (k - 256)];
    g_Ccat[idx] = __float2half_rn(v);
}

__global__ void prep_dh_k(const float* __restrict__ Dm) {
    size_t idx = (size_t)blockIdx.x * blockDim.x + threadIdx.x;   // over 1024*1024
    g_Dh[idx] = __float2half_rn(Dm[idx]);
}

__global__ void transpose_k(const float* __restrict__ in, __half* __restrict__ out,
                            int R, int Cc) {   // out[c*R+r] = h(in[r*Cc+c])
    __shared__ float t[32][33];
    int c0 = blockIdx.x * 32, r0 = blockIdx.y * 32;
    int x = threadIdx.x, y0 = threadIdx.y;
    for (int yy = y0; yy < 32; yy += 8)
        t[yy][x] = in[(size_t)(r0 + yy) * Cc + c0 + x];
    __syncthreads();
    for (int yy = y0; yy < 32; yy += 8)
        out[(size_t)(c0 + yy) * R + r0 + x] = __float2half_rn(t[x][yy]);
}

__global__ void xcopy_k(const float* __restrict__ x) {  // x -> g_xh (fp16)
    size_t i = (size_t)blockIdx.x * blockDim.x + threadIdx.x;   // over M*DM/8
    size_t el = i * 8;
    const float4 v0 = ((const float4*)(x + el))[0];
    const float4 v1 = ((const float4*)(x + el))[1];
    __half2 h0 = __floats2half2_rn(v0.x, v0.y);
    __half2 h1 = __floats2half2_rn(v0.z, v0.w);
    __half2 h2 = __floats2half2_rn(v1.x, v1.y);
    __half2 h3 = __floats2half2_rn(v1.z, v1.w);
    uint4 pk;
    pk.x = *(uint32_t*)&h0; pk.y = *(uint32_t*)&h1;
    pk.z = *(uint32_t*)&h2; pk.w = *(uint32_t*)&h3;
    *(uint4*)(g_xh + el) = pk;
}

// ---------------- fp16 mma.sync GEMM: 128x128x32 + ldmatrix, 4-stage ---------
#define BM 128
#define BN 128
#define BK 32
#define STG 4
#define PADKh 40
#define TILE_H (128 * PADKh)               // 5120 halves
#define STAGE_H (2 * TILE_H)               // 10240 halves
#define SMEM_BYTES (STG * STAGE_H * 2)     // 81920 -> 2 CTAs/SM (164KB)

template<int EPI>
__global__ __launch_bounds__(256, 2)
void mma_gemm(const __half* __restrict__ A, const __half* __restrict__ Bw,
              void* __restrict__ Cv, int N, int K, int lda,
              const float* __restrict__ X, const float* __restrict__ res_logit)
{
    extern __shared__ __half smh[];
    const int tid  = threadIdx.x;
    const int wid  = tid >> 5, lane = tid & 31;
    const int m0 = blockIdx.y * BM, n0 = blockIdx.x * BN;
    const int wm = (wid & 3) * 32, wn = (wid >> 2) * 64;
    const int r = lane >> 2, cq = lane & 3;

    const int lr = tid >> 1;
    const int lch = (tid & 1) * 16;
    const __half* Ag = A + (size_t)(m0 + lr) * lda + lch;
    const __half* Bg = Bw + (size_t)(n0 + lr) * K + lch;
    const uint32_t sbase = smem_u32(smh);
    const uint32_t sAoff = (lr * PADKh + lch) * 2;
    const uint32_t sBoff = (TILE_H + lr * PADKh + lch) * 2;

    // ldmatrix per-lane offset (bytes): row = lane&15, k-half = (lane>>4)*8
    const uint32_t lmoff = (((lane & 15) * PADKh) + (lane >> 4) * 8) * 2;

    float acc[2][8][4];
#pragma unroll
    for (int mt = 0; mt < 2; mt++)
#pragma unroll
        for (int nt = 0; nt < 8; nt++)
#pragma unroll
            for (int i = 0; i < 4; i++) acc[mt][nt][i] = 0.f;

    const int KT = K / BK;

#pragma unroll
    for (int s = 0; s < STG - 1; s++) {
        const int k0 = s * BK;
        const uint32_t sb = sbase + s * STAGE_H * 2;
        cp_async16(sb + sAoff,      Ag + k0);
        cp_async16(sb + sAoff + 16, Ag + k0 + 8);
        cp_async16(sb + sBoff,      Bg + k0);
        cp_async16(sb + sBoff + 16, Bg + k0 + 8);
        cp_commit();
    }

    for (int kt = 0; kt < KT; kt++) {
        cp_wait2();
        __syncthreads();

        const int kp = kt + STG - 1;
        if (kp < KT) {
            const int k0 = kp * BK;
            const uint32_t sb = sbase + (kp % STG) * STAGE_H * 2;
            cp_async16(sb + sAoff,      Ag + k0);
            cp_async16(sb + sAoff + 16, Ag + k0 + 8);
            cp_async16(sb + sBoff,      Bg + k0);
            cp_async16(sb + sBoff + 16, Bg + k0 + 8);
        }
        cp_commit();

        const uint32_t sAb = sbase + (kt % STG) * STAGE_H * 2;
        const uint32_t sBb = sAb + TILE_H * 2;
#pragma unroll
        for (int ks = 0; ks < 2; ks++) {
            uint32_t af[2][4], bf[8][2];
#pragma unroll
            for (int mt = 0; mt < 2; mt++) {
                const uint32_t addr = sAb + ((wm + mt * 16) * PADKh + ks * 16) * 2 + lmoff;
                ldsm_x4(af[mt][0], af[mt][1], af[mt][2], af[mt][3], addr);
            }
#pragma unroll
            for (int ntp = 0; ntp < 4; ntp++) {
                const uint32_t addr = sBb + ((wn + ntp * 16) * PADKh + ks * 16) * 2 + lmoff;
                ldsm_x4(bf[2 * ntp][0], bf[2 * ntp + 1][0],
                        bf[2 * ntp][1], bf[2 * ntp + 1][1], addr);
            }
#pragma unroll
            for (int mt = 0; mt < 2; mt++)
#pragma unroll
                for (int nt = 0; nt < 8; nt++)
                    mma_f16(acc[mt][nt], af[mt], bf[nt]);
        }
    }

    float sig = 0.f;
    if (EPI == EPI_RESID) sig = 1.f / (1.f + expf(-res_logit[0]));

#pragma unroll
    for (int mt = 0; mt < 2; mt++)
#pragma unroll
        for (int nt = 0; nt < 8; nt++) {
            const int row = m0 + wm + mt * 16 + r;
            const int col = n0 + wn + nt * 8 + cq * 2;
#pragma unroll
            for (int h = 0; h < 2; h++) {
                const size_t off = (size_t)(row + h * 8) * N + col;
                float v0 = acc[mt][nt][h * 2 + 0];
                float v1 = acc[mt][nt][h * 2 + 1];
                if (EPI == EPI_F32) {
                    *(float2*)((float*)Cv + off) = make_float2(v0, v1);
                } else if (EPI == EPI_HALF) {
                    *(__half2*)((__half*)Cv + off) = __floats2half2_rn(v0, v1);
                } else if (EPI == EPI_ADDH) {
                    __half2 old = *(__half2*)((__half*)Cv + off);
                    float2 of = __half22float2(old);
                    *(__half2*)((__half*)Cv + off) = __floats2half2_rn(of.x + v0, of.y + v1);
                } else if (EPI == EPI_GELUH) {
                    *(__half2*)((__half*)Cv + off) =
                        __floats2half2_rn(gelu_fast(v0), gelu_fast(v1));
                } else {
                    float2 xv = *(const float2*)(X + off);
                    *(float2*)((float*)Cv + off) =
                        make_float2(xv.x + sig * v0, xv.y + sig * v1);
                }
            }
        }
}

// ---------------- chunked complex scan (fp32 arithmetic, fp16 I/O) -----------
__device__ __forceinline__ float2 cmul(float2 a, float2 b) {
    return make_float2(a.x * b.x - a.y * b.y, a.x * b.y + a.y * b.x);
}

__global__ void scan1_k() {
    int b = blockIdx.y, chk = blockIdx.x, n = threadIdx.x;
    float2 lam = g_lam[n];
    float2 s = make_float2(0.f, 0.f);
    size_t base = ((size_t)(b * L_SZ + chk * CH)) * 512;
    for (int i = 0; i < CH; i++) {
        size_t ib = base + (size_t)i * 512;
        float ur = __half2float(g_Bu[ib + n]);
        float ui = __half2float(g_Bu[ib + 256 + n]);
        s = make_float2(lam.x * s.x - lam.y * s.y + ur,
                        lam.x * s.y + lam.y * s.x + ui);
    }
    g_final[(b * NCHUNK + chk) * DS + n] = s;
}

__global__ void scan2_k() {
    int b = blockIdx.x, n = threadIdx.x;
    float2 lam = g_lam[n];
    float2 lc = lam;
#pragma unroll
    for (int t = 0; t < 5; t++) lc = cmul(lc, lc);   // lam^32 (CH = 32 = 2^5)
    float2 c = make_float2(0.f, 0.f);
    for (int j = 0; j < NCHUNK; j++) {
        g_carry[(b * NCHUNK + j) * DS + n] = c;
        float2 f = g_final[(b * NCHUNK + j) * DS + n];
        c = make_float2(lc.x * c.x - lc.y * c.y + f.x,
                        lc.x * c.y + lc.y * c.x + f.y);
    }
}

__global__ void scan3_k(float* __restrict__ st_out, int st_mode) {
    int b = blockIdx.y, chk = blockIdx.x, n = threadIdx.x;
    float2 lam = g_lam[n];
    float2 s = g_carry[(b * NCHUNK + chk) * DS + n];
    size_t base = ((size_t)(b * L_SZ + chk * CH)) * 512;
    for (int i = 0; i < CH; i++) {
        size_t ib = base + (size_t)i * 512;
        float ur = __half2float(g_Bu[ib + n]);
        float ui = __half2float(g_Bu[ib + 256 + n]);
        s = make_float2(lam.x * s.x - lam.y * s.y + ur,
                        lam.x * s.y + lam.y * s.x + ui);
        g_S[ib + n]       = __float2half_rn(s.x);
        g_S[ib + 256 + n] = __float2half_rn(s.y);
    }
    if (chk == NCHUNK - 1 && st_mode > 0) {
        st_out[b * DS + n] = s.x;
        if (st_mode == 2) st_out[B_SZ * DS + b * DS + n] = s.y;
    }
}

// ---------------- launch ----------------------------------------------------
extern "C" void kernel_launch(void* const* d_in, const int* in_sizes, int n_in,
                              void* d_out, int out_size)
{
    const float* x    = (const float*)d_in[0];
    const float* nu   = (const float*)d_in[1];
    const float* th   = (const float*)d_in[2];
    const float* Bre  = (const float*)d_in[3];
    const float* Bim  = (const float*)d_in[4];
    const float* Cre  = (const float*)d_in[5];
    const float* Cim  = (const float*)d_in[6];
    const float* Dm   = (const float*)d_in[7];
    const float* W1   = (const float*)d_in[8];
    const float* W2   = (const float*)d_in[9];
    const float* rlog = (const float*)d_in[10];
    float* out = (float*)d_out;

    __half *xh, *bu, *S, *y, *h, *bcat, *ccat, *dh, *w1t, *w2t;
    cudaGetSymbolAddress((void**)&xh,   g_xh);
    cudaGetSymbolAddress((void**)&bu,   g_Bu);
    cudaGetSymbolAddress((void**)&S,    g_S);
    cudaGetSymbolAddress((void**)&y,    g_y);
    cudaGetSymbolAddress((void**)&h,    g_h);
    cudaGetSymbolAddress((void**)&bcat, g_Bcat);
    cudaGetSymbolAddress((void**)&ccat, g_Ccat);
    cudaGetSymbolAddress((void**)&dh,   g_Dh);
    cudaGetSymbolAddress((void**)&w1t,  g_W1T);
    cudaGetSymbolAddress((void**)&w2t,  g_W2T);

    cudaFuncSetAttribute(mma_gemm<EPI_HALF>,  cudaFuncAttributeMaxDynamicSharedMemorySize, SMEM_BYTES);
    cudaFuncSetAttribute(mma_gemm<EPI_ADDH>,  cudaFuncAttributeMaxDynamicSharedMemorySize, SMEM_BYTES);
    cudaFuncSetAttribute(mma_gemm<EPI_GELUH>, cudaFuncAttributeMaxDynamicSharedMemorySize, SMEM_BYTES);
    cudaFuncSetAttribute(mma_gemm<EPI_RESID>, cudaFuncAttributeMaxDynamicSharedMemorySize, SMEM_BYTES);

    static cudaStream_t s_side = 0;
    static cudaEvent_t ev_fork = 0, ev_x = 0, ev_join = 0;
    if (s_side == 0) {
        cudaStreamCreateWithFlags(&s_side, cudaStreamNonBlocking);
        cudaEventCreateWithFlags(&ev_fork, cudaEventDisableTiming);
        cudaEventCreateWithFlags(&ev_x,    cudaEventDisableTiming);
        cudaEventCreateWithFlags(&ev_join, cudaEventDisableTiming);
    }

    // fork side stream at entry (weight prep independent of main chain)
    cudaEventRecord(ev_fork, 0);
    cudaStreamWaitEvent(s_side, ev_fork, 0);
    prep_dh_k<<<(DM * DM) / 256, 256, 0, s_side>>>(Dm);
    prep_ccat_k<<<(DM * 512) / 256, 256, 0, s_side>>>(Cre, Cim);
    transpose_k<<<dim3(DH / 32, DM / 32), dim3(32, 8), 0, s_side>>>(W1, w1t, DM, DH);
    transpose_k<<<dim3(DM / 32, DH / 32), dim3(32, 8), 0, s_side>>>(W2, w2t, DH, DM);

    // main chain: lam/gamma -> Bcat, xh
    precompute_k<<<1, DS>>>(nu, th);
    prep_bcat_k<<<(512 * DM) / 256, 256>>>(Bre, Bim);
    xcopy_k<<<((size_t)M_ROWS * DM / 8) / 256, 256>>>(x);
    cudaEventRecord(ev_x, 0);

    // side: y1 = xh @ D^T (independent of scan; overlaps Bu GEMM + scan)
    cudaStreamWaitEvent(s_side, ev_x, 0);
    mma_gemm<EPI_HALF><<<dim3(DM / BN, M_ROWS / BM), 256, SMEM_BYTES, s_side>>>(
        xh, dh, y, DM, DM, DM, nullptr, nullptr);
    cudaEventRecord(ev_join, s_side);

    // main: Bu GEMM -> scan
    mma_gemm<EPI_HALF><<<dim3(512 / BN, M_ROWS / BM), 256, SMEM_BYTES>>>(
        xh, bcat, bu, 512, DM, DM, nullptr, nullptr);
    scan1_k<<<dim3(NCHUNK, B_SZ), DS>>>();
    scan2_k<<<B_SZ, DS>>>();
    long long tail = (long long)out_size - (long long)M_ROWS * DM;
    int st_mode = (tail >= 2 * B_SZ * DS) ? 2 : (tail >= B_SZ * DS ? 1 : 0);
    scan3_k<<<dim3(NCHUNK, B_SZ), DS>>>(out + (size_t)M_ROWS * DM, st_mode);

    // join: y2 needs y1 (and Ccat)
    cudaStreamWaitEvent(0, ev_join, 0);

    // y += S @ Ccat^T   (K=512, read-modify-write fp16)
    mma_gemm<EPI_ADDH><<<dim3(DM / BN, M_ROWS / BM), 256, SMEM_BYTES>>>(
        S, ccat, y, DM, 512, 512, nullptr, nullptr);

    // h = gelu(y @ W1T^T)
    mma_gemm<EPI_GELUH><<<dim3(DH / BN, M_ROWS / BM), 256, SMEM_BYTES>>>(
        y, w1t, h, DH, DM, DM, nullptr, nullptr);

    // out = x + sigmoid(res_logit) * (h @ W2T^T)
    mma_gemm<EPI_RESID><<<dim3(DM / BN, M_ROWS / BM), 256, SMEM_BYTES>>>(
        h, w2t, out, DM, DH, DH, x, rlog);
}